// round 7
// baseline (speedup 1.0000x reference)
#include <cuda_runtime.h>
#include <cuda_bf16.h>
#include <cstdint>

#define BATCH  4096
#define NREL   128
#define EMB    256
#define KDIM   512
#define NITER  8          // 16 K-chunks of 64, two per iteration
#define NS     4          // B pipeline stages (16 KB each)

// ---------------- device globals ----------------
// B pre-packed: [2 ntiles][16 chunks][64 rows x 128B, swizzled]   (256 KB)
__device__ __align__(128) __nv_bfloat16 g_Bs[NREL * 1024];
__device__ __align__(16) float g_const[NREL];

// ---------------- helpers ----------------
__device__ __forceinline__ uint32_t smem_u32(const void* p) {
    uint32_t a;
    asm("{ .reg .u64 t; cvta.to.shared.u64 t, %1; cvt.u32.u64 %0, t; }" : "=r"(a) : "l"(p));
    return a;
}
__device__ __forceinline__ void ldsm_x4(uint32_t& r0, uint32_t& r1, uint32_t& r2, uint32_t& r3,
                                        uint32_t addr) {
    asm volatile("ldmatrix.sync.aligned.m8n8.x4.shared.b16 {%0,%1,%2,%3}, [%4];"
                 : "=r"(r0), "=r"(r1), "=r"(r2), "=r"(r3) : "r"(addr));
}
__device__ __forceinline__ void mma16816(float* d, const uint32_t* a, uint32_t b0, uint32_t b1) {
    asm volatile(
        "mma.sync.aligned.m16n8k16.row.col.f32.bf16.bf16.f32 "
        "{%0,%1,%2,%3}, {%4,%5,%6,%7}, {%8,%9}, {%0,%1,%2,%3};"
        : "+f"(d[0]), "+f"(d[1]), "+f"(d[2]), "+f"(d[3])
        : "r"(a[0]), "r"(a[1]), "r"(a[2]), "r"(a[3]), "r"(b0), "r"(b1));
}
#define MBAR_INIT(addr, cnt) \
    asm volatile("mbarrier.init.shared.b64 [%0], %1;" :: "r"(addr), "r"((uint32_t)(cnt)) : "memory")
#define MBAR_EXPECT_TX(addr, bytes) \
    asm volatile("mbarrier.arrive.expect_tx.shared.b64 _, [%0], %1;" :: "r"(addr), "r"((uint32_t)(bytes)) : "memory")
#define MBAR_WAIT(addr, par) do { \
    uint32_t _m = (addr); uint32_t _p = (par); uint32_t _d; \
    asm volatile("{\n\t.reg .pred p;\n\tmbarrier.try_wait.parity.acquire.cta.shared::cta.b64 p, [%1], %2;\n\tselp.b32 %0, 1, 0, p;\n\t}" \
        : "=r"(_d) : "r"(_m), "r"(_p) : "memory"); \
    if (!_d) { \
        asm volatile("{\n\t.reg .pred P1;\n\tWL_%=: \n\tmbarrier.try_wait.parity.acquire.cta.shared::cta.b64 P1, [%0], %1, 0x989680;\n\t@P1 bra.uni WD_%=;\n\tbra.uni WL_%=;\n\tWD_%=: \n\t}" \
            :: "r"(_m), "r"(_p) : "memory"); \
    } } while (0)
#define CP_BULK(dst, src, sz, mbar) \
    asm volatile("cp.async.bulk.shared::cta.global.mbarrier::complete_tx::bytes [%0], [%1], %2, [%3];" \
        :: "r"(dst), "l"(src), "r"((uint32_t)(sz)), "r"(mbar) : "memory")

#define SWZ(bo) ((bo) ^ (((bo) >> 3) & 0x70))

// ---------------- prep: pack B + const (one block per relation) ----------------
__global__ void prep_B(const float* __restrict__ mus,
                       const float* __restrict__ sigmas,
                       const float* __restrict__ priors) {
    const int r = blockIdx.x;          // 0..127
    const int t = threadIdx.x;         // 0..255
    const int nt  = r >> 6;            // ntile
    const int rin = r & 63;
    char* base = reinterpret_cast<char*>(g_Bs);

    float part = 0.0f;
    #pragma unroll
    for (int i = 0; i < 2; i++) {
        const int k = t + i * 256;     // 0..511
        const float s    = sigmas[r * KDIM + k];
        const float mu   = mus[r * KDIM + k];
        const float inv2 = 1.0f / (s * s);
        const int c  = k >> 6;
        const uint32_t off = SWZ((uint32_t)(rin * 128 + (k & 63) * 2));
        *reinterpret_cast<__nv_bfloat16*>(base + ((size_t)nt * 16 + c)     * 8192 + off)
            = __float2bfloat16(-0.5f * inv2);        // w2 <-> x^2
        *reinterpret_cast<__nv_bfloat16*>(base + ((size_t)nt * 16 + c + 8) * 8192 + off)
            = __float2bfloat16(mu * inv2);           // w1 <-> x
        part += -0.5f * mu * mu * inv2 - logf(s) - 0.9189385332046727f;
    }

    __shared__ float red[8];
    #pragma unroll
    for (int off = 16; off > 0; off >>= 1)
        part += __shfl_down_sync(0xffffffffu, part, off);
    if ((t & 31) == 0) red[t >> 5] = part;
    __syncthreads();
    if (t < 8) {
        float v = red[t];
        #pragma unroll
        for (int off = 4; off > 0; off >>= 1)
            v += __shfl_down_sync(0x000000ffu, v, off);
        if (t == 0) g_const[r] = v + priors[r] * (float)KDIM;
    }
}

// ---------------- main ----------------
// smem: A chunk-tiles [16][64 rows x 128B] = 128 KB, B stages [NS][16 KB], mbars
#define SMA_BYTES   131072
#define SMB_OFF     SMA_BYTES
#define MBAR_OFF    (SMA_BYTES + NS * 16384)
#define SMEM_TOTAL  (MBAR_OFF + 64)

__global__ __launch_bounds__(512)
void nb_mma(const float* __restrict__ sbjs,
            const float* __restrict__ objs,
            float* __restrict__ out) {
    extern __shared__ char smem[];
    const uint32_t sb = smem_u32(smem);

    const int tid  = threadIdx.x;
    const int lane = tid & 31;
    const int wid  = tid >> 5;              // 0..15
    const int mtile = blockIdx.x >> 1;      // 0..63
    const int ntile = blockIdx.x & 1;       // 0..1

    if (tid == 0) {
        #pragma unroll
        for (int s = 0; s < NS; s++) MBAR_INIT(sb + MBAR_OFF + s * 8, 1);
    }
    __syncthreads();

    const char* bSrc = reinterpret_cast<const char*>(g_Bs) + (size_t)ntile * 16 * 8192;
    auto issueB = [&](int it) {
        const int s = it % NS;
        const uint32_t mb = sb + MBAR_OFF + s * 8;
        MBAR_EXPECT_TX(mb, 16384);
        CP_BULK(sb + SMB_OFF + s * 16384, bSrc + (size_t)(2 * it) * 8192, 16384, mb);
    };
    if (tid == 0) {
        issueB(0); issueB(1); issueB(2);
    }

    // ---- A preload: 64 rows x 512 floats -> [x^2 ; x] bf16 chunk-tiles ----
    {
        const int arow = tid >> 3;           // 0..63
        const int k0   = (tid & 7) * 64;     // 0,64,...,448 (never straddles EMB)
        const float* src = (k0 < EMB) ? sbjs + (size_t)(mtile * 64 + arow) * EMB + k0
                                      : objs + (size_t)(mtile * 64 + arow) * EMB + (k0 - EMB);
        const int c = k0 >> 6;               // chunk 0..7
        char* dsq = smem + (size_t)c * 8192;
        char* drw = smem + (size_t)(c + 8) * 8192;
        #pragma unroll
        for (int j = 0; j < 16; j++) {
            const float4 v = reinterpret_cast<const float4*>(src)[j];
            __nv_bfloat162 r0 = __floats2bfloat162_rn(v.x, v.y);
            __nv_bfloat162 r1 = __floats2bfloat162_rn(v.z, v.w);
            __nv_bfloat162 q0 = __floats2bfloat162_rn(v.x * v.x, v.y * v.y);
            __nv_bfloat162 q1 = __floats2bfloat162_rn(v.z * v.z, v.w * v.w);
            const uint32_t off = SWZ((uint32_t)(arow * 128 + (j * 4) * 2));
            uint2 uq, ur;
            uq.x = *reinterpret_cast<uint32_t*>(&q0); uq.y = *reinterpret_cast<uint32_t*>(&q1);
            ur.x = *reinterpret_cast<uint32_t*>(&r0); ur.y = *reinterpret_cast<uint32_t*>(&r1);
            *reinterpret_cast<uint2*>(dsq + off) = uq;
            *reinterpret_cast<uint2*>(drw + off) = ur;
        }
    }

    // ---- compute mappings: 16 warps as 4(m) x 4(n), warp tile 16x16 ----
    const int wm = wid & 3;
    const int wn = wid >> 2;
    const int mrow = wm * 16 + (lane & 15);
    const uint32_t aLdRow = (uint32_t)(mrow * 128);
    const uint32_t aLdXor = (uint32_t)((mrow & 7) << 4);
    const uint32_t aLdBlk = (uint32_t)((lane >> 4) * 16);

    const int nrow = wn * 16 + ((lane >> 4) * 8) + (lane & 7);
    const uint32_t bLdRow = (uint32_t)(nrow * 128);
    const uint32_t bLdXor = (uint32_t)((nrow & 7) << 4);
    const uint32_t bLdBlk = (uint32_t)(((lane >> 3) & 1) * 16);

    float acc[2][4];
    #pragma unroll
    for (int i = 0; i < 2; i++)
        #pragma unroll
        for (int j = 0; j < 4; j++) acc[i][j] = 0.0f;

    // ---- main loop: 8 iterations x 2 chunks ----
    for (int it = 0; it < NITER; it++) {
        const int s = it % NS;
        MBAR_WAIT(sb + MBAR_OFF + s * 8, (it / NS) & 1);
        __syncthreads();                      // also covers A residency on it==0
        if (tid == 0 && it + NS - 1 < NITER) issueB(it + NS - 1);

        #pragma unroll
        for (int kc = 0; kc < 2; kc++) {
            const uint32_t aB = sb + (uint32_t)(2 * it + kc) * 8192;
            const uint32_t bB = sb + SMB_OFF + s * 16384 + kc * 8192;
            #pragma unroll
            for (int ks = 0; ks < 4; ks++) {
                const uint32_t kcol = (uint32_t)(ks * 32);
                uint32_t a[4];
                ldsm_x4(a[0], a[1], a[2], a[3], aB + aLdRow + ((kcol + aLdBlk) ^ aLdXor));
                uint32_t b[4];
                ldsm_x4(b[0], b[1], b[2], b[3], bB + bLdRow + ((kcol + bLdBlk) ^ bLdXor));
                mma16816(acc[0], a, b[0], b[1]);
                mma16816(acc[1], a, b[2], b[3]);
            }
        }
    }

    // ---- epilogue ----
    #pragma unroll
    for (int nf = 0; nf < 2; nf++) {
        const int n0 = ntile * 64 + wn * 16 + nf * 8 + (lane & 3) * 2;
        const float c0 = g_const[n0], c1 = g_const[n0 + 1];
        const int r0 = mtile * 64 + wm * 16 + (lane >> 2);
        float2 o0, o1;
        o0.x = acc[nf][0] + c0; o0.y = acc[nf][1] + c1;
        o1.x = acc[nf][2] + c0; o1.y = acc[nf][3] + c1;
        *reinterpret_cast<float2*>(&out[(size_t)r0 * NREL + n0])       = o0;
        *reinterpret_cast<float2*>(&out[(size_t)(r0 + 8) * NREL + n0]) = o1;
    }
}

extern "C" void kernel_launch(void* const* d_in, const int* in_sizes, int n_in,
                              void* d_out, int out_size) {
    const float* sbjs   = (const float*)d_in[0];
    const float* objs   = (const float*)d_in[1];
    const float* mus    = (const float*)d_in[2];
    const float* sigmas = (const float*)d_in[3];
    const float* priors = (const float*)d_in[4];
    float* out = (float*)d_out;

    cudaFuncSetAttribute(nb_mma, cudaFuncAttributeMaxDynamicSharedMemorySize, SMEM_TOTAL);

    prep_B<<<NREL, 256>>>(mus, sigmas, priors);
    nb_mma<<<128, 512, SMEM_TOTAL>>>(sbjs, objs, out);
    (void)in_sizes; (void)n_in; (void)out_size;
}

// round 8
// speedup vs baseline: 1.4047x; 1.4047x over previous
#include <cuda_runtime.h>
#include <cuda_bf16.h>
#include <cstdint>

#define BATCH  4096
#define NREL   128
#define EMB    256
#define KDIM   512
#define NITER  8          // 8 segments of 64 source floats; pair [x^2_seg, x_seg]
#define NS     4          // B pipeline stages (16 KB each)

// ---------------- device globals ----------------
// B pre-packed: [2 ntiles][8 segs][ w2-tile 8K | w1-tile 8K ]  (256 KB)
__device__ __align__(128) __nv_bfloat16 g_Bs[NREL * 1024];
__device__ __align__(16) float g_const[NREL];

// ---------------- helpers ----------------
__device__ __forceinline__ uint32_t smem_u32(const void* p) {
    uint32_t a;
    asm("{ .reg .u64 t; cvta.to.shared.u64 t, %1; cvt.u32.u64 %0, t; }" : "=r"(a) : "l"(p));
    return a;
}
__device__ __forceinline__ void ldsm_x4(uint32_t& r0, uint32_t& r1, uint32_t& r2, uint32_t& r3,
                                        uint32_t addr) {
    asm volatile("ldmatrix.sync.aligned.m8n8.x4.shared.b16 {%0,%1,%2,%3}, [%4];"
                 : "=r"(r0), "=r"(r1), "=r"(r2), "=r"(r3) : "r"(addr));
}
__device__ __forceinline__ void mma16816(float* d, const uint32_t* a, uint32_t b0, uint32_t b1) {
    asm volatile(
        "mma.sync.aligned.m16n8k16.row.col.f32.bf16.bf16.f32 "
        "{%0,%1,%2,%3}, {%4,%5,%6,%7}, {%8,%9}, {%0,%1,%2,%3};"
        : "+f"(d[0]), "+f"(d[1]), "+f"(d[2]), "+f"(d[3])
        : "r"(a[0]), "r"(a[1]), "r"(a[2]), "r"(a[3]), "r"(b0), "r"(b1));
}
#define MBAR_INIT(addr, cnt) \
    asm volatile("mbarrier.init.shared.b64 [%0], %1;" :: "r"(addr), "r"((uint32_t)(cnt)) : "memory")
#define MBAR_EXPECT_TX(addr, bytes) \
    asm volatile("mbarrier.arrive.expect_tx.shared.b64 _, [%0], %1;" :: "r"(addr), "r"((uint32_t)(bytes)) : "memory")
#define MBAR_WAIT(addr, par) do { \
    uint32_t _m = (addr); uint32_t _p = (par); uint32_t _d; \
    asm volatile("{\n\t.reg .pred p;\n\tmbarrier.try_wait.parity.acquire.cta.shared::cta.b64 p, [%1], %2;\n\tselp.b32 %0, 1, 0, p;\n\t}" \
        : "=r"(_d) : "r"(_m), "r"(_p) : "memory"); \
    if (!_d) { \
        asm volatile("{\n\t.reg .pred P1;\n\tWL_%=: \n\tmbarrier.try_wait.parity.acquire.cta.shared::cta.b64 P1, [%0], %1, 0x989680;\n\t@P1 bra.uni WD_%=;\n\tbra.uni WL_%=;\n\tWD_%=: \n\t}" \
            :: "r"(_m), "r"(_p) : "memory"); \
    } } while (0)
#define CP_BULK(dst, src, sz, mbar) \
    asm volatile("cp.async.bulk.shared::cta.global.mbarrier::complete_tx::bytes [%0], [%1], %2, [%3];" \
        :: "r"(dst), "l"(src), "r"((uint32_t)(sz)), "r"(mbar) : "memory")

#define SWZ(bo) ((bo) ^ (((bo) >> 3) & 0x70))

// ---------------- prep: pack B + const (one block per relation) ----------------
// Pack order: [ntile][seg][w2 8K | w1 8K], tiles 64 rows x 128B swizzled.
__global__ void prep_B(const float* __restrict__ mus,
                       const float* __restrict__ sigmas,
                       const float* __restrict__ priors) {
    const int r = blockIdx.x;          // 0..127
    const int t = threadIdx.x;         // 0..255
    const int nt  = r >> 6;            // ntile
    const int rin = r & 63;
    char* base = reinterpret_cast<char*>(g_Bs) + (size_t)nt * 8 * 16384;

    float part = 0.0f;
    #pragma unroll
    for (int i = 0; i < 2; i++) {
        const int k = t + i * 256;     // 0..511
        const float s    = sigmas[r * KDIM + k];
        const float mu   = mus[r * KDIM + k];
        const float inv2 = 1.0f / (s * s);
        const int seg = k >> 6;
        const uint32_t off = SWZ((uint32_t)(rin * 128 + (k & 63) * 2));
        *reinterpret_cast<__nv_bfloat16*>(base + (size_t)seg * 16384 + off)
            = __float2bfloat16(-0.5f * inv2);        // w2 <-> x^2
        *reinterpret_cast<__nv_bfloat16*>(base + (size_t)seg * 16384 + 8192 + off)
            = __float2bfloat16(mu * inv2);           // w1 <-> x
        part += -0.5f * mu * mu * inv2 - logf(s) - 0.9189385332046727f;
    }

    __shared__ float red[8];
    #pragma unroll
    for (int off = 16; off > 0; off >>= 1)
        part += __shfl_down_sync(0xffffffffu, part, off);
    if ((t & 31) == 0) red[t >> 5] = part;
    __syncthreads();
    if (t < 8) {
        float v = red[t];
        #pragma unroll
        for (int off = 4; off > 0; off >>= 1)
            v += __shfl_down_sync(0x000000ffu, v, off);
        if (t == 0) g_const[r] = v + priors[r] * (float)KDIM;
    }
}

// ---------------- main ----------------
// smem: A buffers [2][x^2 8K | x 8K] = 32 KB, B stages [NS][16 KB] = 64 KB, mbars
#define SMB_OFF     32768
#define MBAR_OFF    (SMB_OFF + NS * 16384)
#define SMEM_TOTAL  (MBAR_OFF + 64)

__global__ __launch_bounds__(512)
void nb_mma(const float* __restrict__ sbjs,
            const float* __restrict__ objs,
            float* __restrict__ out) {
    extern __shared__ char smem[];
    const uint32_t sb = smem_u32(smem);

    const int tid  = threadIdx.x;
    const int lane = tid & 31;
    const int wid  = tid >> 5;              // 0..15
    const int mtile = blockIdx.x >> 1;      // 0..63
    const int ntile = blockIdx.x & 1;       // 0..1

    if (tid == 0) {
        #pragma unroll
        for (int s = 0; s < NS; s++) MBAR_INIT(sb + MBAR_OFF + s * 8, 1);
    }
    __syncthreads();

    // ---- B issue (bulk engine, 16 KB pack per iteration) ----
    const char* bSrc = reinterpret_cast<const char*>(g_Bs) + (size_t)ntile * 8 * 16384;
    auto issueB = [&](int it) {
        const int s = it % NS;
        const uint32_t mb = sb + MBAR_OFF + s * 8;
        MBAR_EXPECT_TX(mb, 16384);
        CP_BULK(sb + SMB_OFF + s * 16384, bSrc + (size_t)it * 16384, 16384, mb);
    };
    if (tid == 0) { issueB(0); issueB(1); issueB(2); }

    // ---- A loader: 8 consecutive floats per thread per segment ----
    const int arow = tid >> 3;               // 0..63
    const int kq   = (tid & 7) * 8;          // 0..56
    const uint32_t aOff = SWZ((uint32_t)(arow * 128 + kq * 2));   // 16B aligned
    auto ldgA = [&](int seg, float4& v0, float4& v1) {
        const int kg = seg * 64 + kq;
        const float* src = (kg < EMB)
            ? sbjs + (size_t)(mtile * 64 + arow) * EMB + kg
            : objs + (size_t)(mtile * 64 + arow) * EMB + (kg - EMB);
        v0 = reinterpret_cast<const float4*>(src)[0];
        v1 = reinterpret_cast<const float4*>(src)[1];
    };
    auto stsA = [&](int buf, float4 v0, float4 v1) {
        __nv_bfloat162 q0 = __floats2bfloat162_rn(v0.x * v0.x, v0.y * v0.y);
        __nv_bfloat162 q1 = __floats2bfloat162_rn(v0.z * v0.z, v0.w * v0.w);
        __nv_bfloat162 q2 = __floats2bfloat162_rn(v1.x * v1.x, v1.y * v1.y);
        __nv_bfloat162 q3 = __floats2bfloat162_rn(v1.z * v1.z, v1.w * v1.w);
        __nv_bfloat162 r0 = __floats2bfloat162_rn(v0.x, v0.y);
        __nv_bfloat162 r1 = __floats2bfloat162_rn(v0.z, v0.w);
        __nv_bfloat162 r2 = __floats2bfloat162_rn(v1.x, v1.y);
        __nv_bfloat162 r3 = __floats2bfloat162_rn(v1.z, v1.w);
        uint4 uq, ur;
        uq.x = *reinterpret_cast<uint32_t*>(&q0); uq.y = *reinterpret_cast<uint32_t*>(&q1);
        uq.z = *reinterpret_cast<uint32_t*>(&q2); uq.w = *reinterpret_cast<uint32_t*>(&q3);
        ur.x = *reinterpret_cast<uint32_t*>(&r0); ur.y = *reinterpret_cast<uint32_t*>(&r1);
        ur.z = *reinterpret_cast<uint32_t*>(&r2); ur.w = *reinterpret_cast<uint32_t*>(&r3);
        char* dst = smem + (size_t)buf * 16384;
        *reinterpret_cast<uint4*>(dst + aOff)        = uq;   // x^2 tile
        *reinterpret_cast<uint4*>(dst + 8192 + aOff) = ur;   // x tile
    };

    // prologue: segment 0 into A buf 0
    {
        float4 v0, v1;
        ldgA(0, v0, v1);
        stsA(0, v0, v1);
    }

    // ---- compute mappings: 16 warps as 4(m) x 4(n), warp tile 16x16 ----
    const int wm = wid & 3;
    const int wn = wid >> 2;
    const int mrow = wm * 16 + (lane & 15);
    const uint32_t aLdRow = (uint32_t)(mrow * 128);
    const uint32_t aLdXor = (uint32_t)((mrow & 7) << 4);
    const uint32_t aLdBlk = (uint32_t)((lane >> 4) * 16);

    const int nrow = wn * 16 + ((lane >> 4) * 8) + (lane & 7);
    const uint32_t bLdRow = (uint32_t)(nrow * 128);
    const uint32_t bLdXor = (uint32_t)((nrow & 7) << 4);
    const uint32_t bLdBlk = (uint32_t)(((lane >> 3) & 1) * 16);

    float acc[2][4];
    #pragma unroll
    for (int i = 0; i < 2; i++)
        #pragma unroll
        for (int j = 0; j < 4; j++) acc[i][j] = 0.0f;

    // ---- main loop ----
    for (int it = 0; it < NITER; it++) {
        const int s   = it % NS;
        const int buf = it & 1;
        MBAR_WAIT(sb + MBAR_OFF + s * 8, (it / NS) & 1);
        __syncthreads();     // A[buf] visible; prev iter done reading A[buf^1] & B stage
        if (tid == 0 && it + NS - 1 < NITER) issueB(it + NS - 1);

        // prefetch next segment's x into registers (latency hidden by compute)
        float4 pv0, pv1;
        const bool have_next = (it + 1 < NITER);
        if (have_next) ldgA(it + 1, pv0, pv1);

        // compute: pair [x^2 (tile 0) x w2 (tile 0)] and [x (tile 1) x w1 (tile 1)]
        const uint32_t aStage = sb + (uint32_t)buf * 16384;
        const uint32_t bStage = sb + SMB_OFF + (uint32_t)s * 16384;
        #pragma unroll
        for (int kc = 0; kc < 2; kc++) {
            const uint32_t aB = aStage + kc * 8192;
            const uint32_t bB = bStage + kc * 8192;
            #pragma unroll
            for (int ks = 0; ks < 4; ks++) {
                const uint32_t kcol = (uint32_t)(ks * 32);
                uint32_t a[4];
                ldsm_x4(a[0], a[1], a[2], a[3], aB + aLdRow + ((kcol + aLdBlk) ^ aLdXor));
                uint32_t b[4];
                ldsm_x4(b[0], b[1], b[2], b[3], bB + bLdRow + ((kcol + bLdBlk) ^ bLdXor));
                mma16816(acc[0], a, b[0], b[1]);
                mma16816(acc[1], a, b[2], b[3]);
            }
        }

        if (have_next) stsA(buf ^ 1, pv0, pv1);
    }

    // ---- epilogue ----
    #pragma unroll
    for (int nf = 0; nf < 2; nf++) {
        const int n0 = ntile * 64 + wn * 16 + nf * 8 + (lane & 3) * 2;
        const float c0 = g_const[n0], c1 = g_const[n0 + 1];
        const int r0 = mtile * 64 + wm * 16 + (lane >> 2);
        float2 o0, o1;
        o0.x = acc[nf][0] + c0; o0.y = acc[nf][1] + c1;
        o1.x = acc[nf][2] + c0; o1.y = acc[nf][3] + c1;
        *reinterpret_cast<float2*>(&out[(size_t)r0 * NREL + n0])       = o0;
        *reinterpret_cast<float2*>(&out[(size_t)(r0 + 8) * NREL + n0]) = o1;
    }
}

extern "C" void kernel_launch(void* const* d_in, const int* in_sizes, int n_in,
                              void* d_out, int out_size) {
    const float* sbjs   = (const float*)d_in[0];
    const float* objs   = (const float*)d_in[1];
    const float* mus    = (const float*)d_in[2];
    const float* sigmas = (const float*)d_in[3];
    const float* priors = (const float*)d_in[4];
    float* out = (float*)d_out;

    cudaFuncSetAttribute(nb_mma, cudaFuncAttributeMaxDynamicSharedMemorySize, SMEM_TOTAL);

    prep_B<<<NREL, 256>>>(mus, sigmas, priors);
    nb_mma<<<128, 512, SMEM_TOTAL>>>(sbjs, objs, out);
    (void)in_sizes; (void)n_in; (void)out_size;
}

// round 10
// speedup vs baseline: 1.4106x; 1.0043x over previous
#include <cuda_runtime.h>
#include <cuda_bf16.h>
#include <cstdint>

#define BATCH  4096
#define NREL   128
#define EMB    256
#define KDIM   512
#define NITER  8          // 8 segments of 64 source floats; pair [x^2_seg, x_seg]
#define NS     4          // B pipeline stages (16 KB each)

// ---------------- device globals ----------------
// B pre-packed: [2 ntiles][8 segs][ w2-tile 8K | w1-tile 8K ]  (256 KB)
__device__ __align__(128) __nv_bfloat16 g_Bs[NREL * 1024];
__device__ __align__(16) float g_const[NREL];

// ---------------- helpers ----------------
__device__ __forceinline__ uint32_t smem_u32(const void* p) {
    uint32_t a;
    asm("{ .reg .u64 t; cvta.to.shared.u64 t, %1; cvt.u32.u64 %0, t; }" : "=r"(a) : "l"(p));
    return a;
}
__device__ __forceinline__ void ldsm_x4(uint32_t& r0, uint32_t& r1, uint32_t& r2, uint32_t& r3,
                                        uint32_t addr) {
    asm volatile("ldmatrix.sync.aligned.m8n8.x4.shared.b16 {%0,%1,%2,%3}, [%4];"
                 : "=r"(r0), "=r"(r1), "=r"(r2), "=r"(r3) : "r"(addr));
}
__device__ __forceinline__ void mma16816(float* d, const uint32_t* a, uint32_t b0, uint32_t b1) {
    asm volatile(
        "mma.sync.aligned.m16n8k16.row.col.f32.bf16.bf16.f32 "
        "{%0,%1,%2,%3}, {%4,%5,%6,%7}, {%8,%9}, {%0,%1,%2,%3};"
        : "+f"(d[0]), "+f"(d[1]), "+f"(d[2]), "+f"(d[3])
        : "r"(a[0]), "r"(a[1]), "r"(a[2]), "r"(a[3]), "r"(b0), "r"(b1));
}
#define MBAR_INIT(addr, cnt) \
    asm volatile("mbarrier.init.shared.b64 [%0], %1;" :: "r"(addr), "r"((uint32_t)(cnt)) : "memory")
#define MBAR_EXPECT_TX(addr, bytes) \
    asm volatile("mbarrier.arrive.expect_tx.shared.b64 _, [%0], %1;" :: "r"(addr), "r"((uint32_t)(bytes)) : "memory")
#define MBAR_WAIT(addr, par) do { \
    uint32_t _m = (addr); uint32_t _p = (par); uint32_t _d; \
    asm volatile("{\n\t.reg .pred p;\n\tmbarrier.try_wait.parity.acquire.cta.shared::cta.b64 p, [%1], %2;\n\tselp.b32 %0, 1, 0, p;\n\t}" \
        : "=r"(_d) : "r"(_m), "r"(_p) : "memory"); \
    if (!_d) { \
        asm volatile("{\n\t.reg .pred P1;\n\tWL_%=: \n\tmbarrier.try_wait.parity.acquire.cta.shared::cta.b64 P1, [%0], %1, 0x989680;\n\t@P1 bra.uni WD_%=;\n\tbra.uni WL_%=;\n\tWD_%=: \n\t}" \
            :: "r"(_m), "r"(_p) : "memory"); \
    } } while (0)
#define CP_BULK(dst, src, sz, mbar) \
    asm volatile("cp.async.bulk.shared::cta.global.mbarrier::complete_tx::bytes [%0], [%1], %2, [%3];" \
        :: "r"(dst), "l"(src), "r"((uint32_t)(sz)), "r"(mbar) : "memory")

#define SWZ(bo) ((bo) ^ (((bo) >> 3) & 0x70))

// ---------------- prep: pack B + const (one block per relation) ----------------
// Pack order: [ntile][seg][w2 8K | w1 8K], tiles 64 rows x 128B swizzled.
__global__ void prep_B(const float* __restrict__ mus,
                       const float* __restrict__ sigmas,
                       const float* __restrict__ priors) {
    const int r = blockIdx.x;          // 0..127
    const int t = threadIdx.x;         // 0..255
    const int nt  = r >> 6;            // ntile
    const int rin = r & 63;
    char* base = reinterpret_cast<char*>(g_Bs) + (size_t)nt * 8 * 16384;

    float part = 0.0f;
    #pragma unroll
    for (int i = 0; i < 2; i++) {
        const int k = t + i * 256;     // 0..511
        const float s    = sigmas[r * KDIM + k];
        const float mu   = mus[r * KDIM + k];
        const float inv2 = 1.0f / (s * s);
        const int seg = k >> 6;
        const uint32_t off = SWZ((uint32_t)(rin * 128 + (k & 63) * 2));
        *reinterpret_cast<__nv_bfloat16*>(base + (size_t)seg * 16384 + off)
            = __float2bfloat16(-0.5f * inv2);        // w2 <-> x^2
        *reinterpret_cast<__nv_bfloat16*>(base + (size_t)seg * 16384 + 8192 + off)
            = __float2bfloat16(mu * inv2);           // w1 <-> x
        part += -0.5f * mu * mu * inv2 - logf(s) - 0.9189385332046727f;
    }

    __shared__ float red[8];
    #pragma unroll
    for (int off = 16; off > 0; off >>= 1)
        part += __shfl_down_sync(0xffffffffu, part, off);
    if ((t & 31) == 0) red[t >> 5] = part;
    __syncthreads();
    if (t < 8) {
        float v = red[t];
        #pragma unroll
        for (int off = 4; off > 0; off >>= 1)
            v += __shfl_down_sync(0x000000ffu, v, off);
        if (t == 0) g_const[r] = v + priors[r] * (float)KDIM;
    }
}

// ---------------- main ----------------
// CTA tile 32(m) x 64(n), 256 threads, 2 CTAs/SM.
// smem: A buffers [2][x^2 4K | x 4K] = 16 KB, B stages [NS][16 KB] = 64 KB, mbars
#define SMB_OFF     16384
#define MBAR_OFF    (SMB_OFF + NS * 16384)
#define SMEM_TOTAL  (MBAR_OFF + 64)

__global__ __launch_bounds__(256, 2)
void nb_mma(const float* __restrict__ sbjs,
            const float* __restrict__ objs,
            float* __restrict__ out) {
    extern __shared__ char smem[];
    const uint32_t sb = smem_u32(smem);

    const int tid  = threadIdx.x;
    const int lane = tid & 31;
    const int wid  = tid >> 5;              // 0..7
    const int mtile = blockIdx.x >> 1;      // 0..127
    const int ntile = blockIdx.x & 1;       // 0..1

    if (tid == 0) {
        #pragma unroll
        for (int s = 0; s < NS; s++) MBAR_INIT(sb + MBAR_OFF + s * 8, 1);
    }
    __syncthreads();

    // ---- B issue (bulk engine, 16 KB pack per iteration) ----
    const char* bSrc = reinterpret_cast<const char*>(g_Bs) + (size_t)ntile * 8 * 16384;
    auto issueB = [&](int it) {
        const int s = it % NS;
        const uint32_t mb = sb + MBAR_OFF + s * 8;
        MBAR_EXPECT_TX(mb, 16384);
        CP_BULK(sb + SMB_OFF + s * 16384, bSrc + (size_t)it * 16384, 16384, mb);
    };
    if (tid == 0) { issueB(0); issueB(1); issueB(2); }

    // ---- A loader: 8 consecutive floats per thread per segment (32 rows) ----
    const int arow = tid >> 3;               // 0..31
    const int kq   = (tid & 7) * 8;          // 0..56
    const uint32_t aOff = SWZ((uint32_t)(arow * 128 + kq * 2));   // 16B aligned
    auto ldgA = [&](int seg, float4& v0, float4& v1) {
        const int kg = seg * 64 + kq;
        const float* src = (kg < EMB)
            ? sbjs + (size_t)(mtile * 32 + arow) * EMB + kg
            : objs + (size_t)(mtile * 32 + arow) * EMB + (kg - EMB);
        v0 = reinterpret_cast<const float4*>(src)[0];
        v1 = reinterpret_cast<const float4*>(src)[1];
    };
    auto stsA = [&](int buf, float4 v0, float4 v1) {
        __nv_bfloat162 q0 = __floats2bfloat162_rn(v0.x * v0.x, v0.y * v0.y);
        __nv_bfloat162 q1 = __floats2bfloat162_rn(v0.z * v0.z, v0.w * v0.w);
        __nv_bfloat162 q2 = __floats2bfloat162_rn(v1.x * v1.x, v1.y * v1.y);
        __nv_bfloat162 q3 = __floats2bfloat162_rn(v1.z * v1.z, v1.w * v1.w);
        __nv_bfloat162 r0 = __floats2bfloat162_rn(v0.x, v0.y);
        __nv_bfloat162 r1 = __floats2bfloat162_rn(v0.z, v0.w);
        __nv_bfloat162 r2 = __floats2bfloat162_rn(v1.x, v1.y);
        __nv_bfloat162 r3 = __floats2bfloat162_rn(v1.z, v1.w);
        uint4 uq, ur;
        uq.x = *reinterpret_cast<uint32_t*>(&q0); uq.y = *reinterpret_cast<uint32_t*>(&q1);
        uq.z = *reinterpret_cast<uint32_t*>(&q2); uq.w = *reinterpret_cast<uint32_t*>(&q3);
        ur.x = *reinterpret_cast<uint32_t*>(&r0); ur.y = *reinterpret_cast<uint32_t*>(&r1);
        ur.z = *reinterpret_cast<uint32_t*>(&r2); ur.w = *reinterpret_cast<uint32_t*>(&r3);
        char* dst = smem + (size_t)buf * 8192;
        *reinterpret_cast<uint4*>(dst + aOff)        = uq;   // x^2 tile (4 KB)
        *reinterpret_cast<uint4*>(dst + 4096 + aOff) = ur;   // x tile   (4 KB)
    };

    // prologue: segment 0 into A buf 0
    {
        float4 v0, v1;
        ldgA(0, v0, v1);
        stsA(0, v0, v1);
    }

    // ---- compute mappings: 8 warps as 2(m) x 4(n), warp tile 16x16 ----
    const int wm = wid & 1;
    const int wn = wid >> 1;
    const int mrow = wm * 16 + (lane & 15);
    const uint32_t aLdRow = (uint32_t)(mrow * 128);
    const uint32_t aLdXor = (uint32_t)((mrow & 7) << 4);
    const uint32_t aLdBlk = (uint32_t)((lane >> 4) * 16);

    const int nrow = wn * 16 + ((lane >> 4) * 8) + (lane & 7);
    const uint32_t bLdRow = (uint32_t)(nrow * 128);
    const uint32_t bLdXor = (uint32_t)((nrow & 7) << 4);
    const uint32_t bLdBlk = (uint32_t)(((lane >> 3) & 1) * 16);

    float acc[2][4];
    #pragma unroll
    for (int i = 0; i < 2; i++)
        #pragma unroll
        for (int j = 0; j < 4; j++) acc[i][j] = 0.0f;

    // ---- main loop ----
    for (int it = 0; it < NITER; it++) {
        const int s   = it % NS;
        const int buf = it & 1;
        MBAR_WAIT(sb + MBAR_OFF + s * 8, (it / NS) & 1);
        __syncthreads();     // A[buf] visible; prev iter done reading A[buf^1] & B stage
        if (tid == 0 && it + NS - 1 < NITER) issueB(it + NS - 1);

        // prefetch next segment's x into registers (latency hidden by compute)
        float4 pv0, pv1;
        const bool have_next = (it + 1 < NITER);
        if (have_next) ldgA(it + 1, pv0, pv1);

        // compute: pair [x^2 x w2] then [x x w1]
        const uint32_t aStage = sb + (uint32_t)buf * 8192;
        const uint32_t bStage = sb + SMB_OFF + (uint32_t)s * 16384;
        #pragma unroll
        for (int kc = 0; kc < 2; kc++) {
            const uint32_t aB = aStage + kc * 4096;
            const uint32_t bB = bStage + kc * 8192;
            #pragma unroll
            for (int ks = 0; ks < 4; ks++) {
                const uint32_t kcol = (uint32_t)(ks * 32);
                uint32_t a[4];
                ldsm_x4(a[0], a[1], a[2], a[3], aB + aLdRow + ((kcol + aLdBlk) ^ aLdXor));
                uint32_t b[4];
                ldsm_x4(b[0], b[1], b[2], b[3], bB + bLdRow + ((kcol + bLdBlk) ^ bLdXor));
                mma16816(acc[0], a, b[0], b[1]);
                mma16816(acc[1], a, b[2], b[3]);
            }
        }

        if (have_next) stsA(buf ^ 1, pv0, pv1);
    }

    // ---- epilogue ----
    #pragma unroll
    for (int nf = 0; nf < 2; nf++) {
        const int n0 = ntile * 64 + wn * 16 + nf * 8 + (lane & 3) * 2;
        const float c0 = g_const[n0], c1 = g_const[n0 + 1];
        const int r0 = mtile * 32 + wm * 16 + (lane >> 2);
        float2 o0, o1;
        o0.x = acc[nf][0] + c0; o0.y = acc[nf][1] + c1;
        o1.x = acc[nf][2] + c0; o1.y = acc[nf][3] + c1;
        *reinterpret_cast<float2*>(&out[(size_t)r0 * NREL + n0])       = o0;
        *reinterpret_cast<float2*>(&out[(size_t)(r0 + 8) * NREL + n0]) = o1;
    }
}

extern "C" void kernel_launch(void* const* d_in, const int* in_sizes, int n_in,
                              void* d_out, int out_size) {
    const float* sbjs   = (const float*)d_in[0];
    const float* objs   = (const float*)d_in[1];
    const float* mus    = (const float*)d_in[2];
    const float* sigmas = (const float*)d_in[3];
    const float* priors = (const float*)d_in[4];
    float* out = (float*)d_out;

    cudaFuncSetAttribute(nb_mma, cudaFuncAttributeMaxDynamicSharedMemorySize, SMEM_TOTAL);

    prep_B<<<NREL, 256>>>(mus, sigmas, priors);
    nb_mma<<<256, 256, SMEM_TOTAL>>>(sbjs, objs, out);
    (void)in_sizes; (void)n_in; (void)out_size;
}